// round 12
// baseline (speedup 1.0000x reference)
#include <cuda_runtime.h>
#include <math.h>
#include <stdint.h>

#define SK        131072
#define E_CNT     196608
#define H         128
#define N_TOT     4096
#define M_SUB     4
#define K_SUB     8
#define L_LAYERS  4
#define NUM_G     32

// ---------------- scratch (static device memory; no allocations) ----------------
__device__ float g_h[SK * H];     // node features (64 MB)
__device__ float g_aggr[SK * H];  // message aggregation buffer (64 MB)
__device__ float g_mid[SK * H];   // relu intermediate between the two GEMMs (64 MB)

// ---------------- 3xTF32 helpers ----------------
__device__ __forceinline__ void split_tf32(float z, uint32_t& hi, uint32_t& lo) {
    uint32_t zb = __float_as_uint(z);
    hi = zb & 0xFFFFE000u;
    lo = __float_as_uint(z - __uint_as_float(hi));
}

__device__ __forceinline__ void mma_tf32(float* c,
                                         uint32_t a0, uint32_t a1, uint32_t a2, uint32_t a3,
                                         uint32_t b0, uint32_t b1) {
    asm volatile(
        "mma.sync.aligned.m16n8k8.row.col.f32.tf32.tf32.f32 "
        "{%0,%1,%2,%3}, {%4,%5,%6,%7}, {%8,%9}, {%0,%1,%2,%3};"
        : "+f"(c[0]), "+f"(c[1]), "+f"(c[2]), "+f"(c[3])
        : "r"(a0), "r"(a1), "r"(a2), "r"(a3), "r"(b0), "r"(b1));
}

// ================= small kernels =================
__global__ void zero_aggr_kernel() {
    int i = blockIdx.x * blockDim.x + threadIdx.x;
    ((float4*)g_aggr)[i] = make_float4(0.f, 0.f, 0.f, 0.f);
}

__global__ void embed_kernel(const int* __restrict__ x_tokens,
                             const int* __restrict__ node_ids,
                             const float* __restrict__ atom_emb,
                             const float* __restrict__ role_emb) {
    int t = blockIdx.x * blockDim.x + threadIdx.x;
    int node = t >> 5;
    int lane = t & 31;
    int tok = x_tokens[node];
    float vf = (node_ids[node] >= 0) ? 1.0f : 0.0f;
    int is_root = ((node & (K_SUB - 1)) == 0) ? 1 : 0;
    int c = lane * 4;
    float4 a = *(const float4*)(&atom_emb[tok * H + c]);
    float4 r = *(const float4*)(&role_emb[is_root * H + c]);
    float4 o;
    o.x = (a.x + r.x) * vf; o.y = (a.y + r.y) * vf;
    o.z = (a.z + r.z) * vf; o.w = (a.w + r.w) * vf;
    *(float4*)(&g_h[node * H + c]) = o;
}

__global__ void edge_kernel(const int* __restrict__ src,
                            const int* __restrict__ dst,
                            const int* __restrict__ etok,
                            const float* __restrict__ bond_emb) {
    int t = blockIdx.x * blockDim.x + threadIdx.x;
    int e = t >> 5;
    if (e >= E_CNT) return;
    int lane = t & 31;
    int s = src[e], d = dst[e], bt = etok[e];
    int c = lane * 4;
    float4 hv = *(const float4*)(&g_h[s * H + c]);
    float4 bv = *(const float4*)(&bond_emb[bt * H + c]);
    float4 m;
    m.x = fmaxf(hv.x + bv.x, 0.f); m.y = fmaxf(hv.y + bv.y, 0.f);
    m.z = fmaxf(hv.z + bv.z, 0.f); m.w = fmaxf(hv.w + bv.w, 0.f);
    float* zp = &g_aggr[d * H + c];
    asm volatile("red.global.add.v4.f32 [%0], {%1, %2, %3, %4};"
                 :: "l"(zp), "f"(m.x), "f"(m.y), "f"(m.z), "f"(m.w) : "memory");
}

// ================= 3xTF32 mma.sync GEMM (pipelined, 32x32 warp tiles) ==========
// MODE 1: Z=(1+eps)*h+aggr ; out = relu(Z@W1+b1) -> g_mid     (optionally zero aggr)
// MODE 2: Z=g_mid          ; out = (Z@W2+b2)*vf  -> g_h
//
// Persistent (grid=148, 1 block/SM). 256 threads = 8 warps (2 row x 4 col groups).
// Block tile 64x128, warp tile 32x32 (2 m-frags x 4 n-frags) -> W LDS traffic
// halves vs (16,32): per warp-k-step 8 LDS.64 (A) + 4 LDS.128 (W) feed 24 MMAs.
// A: zs (hi,lo) float2, stride 132. W: frag-packed float4 (hi0,lo0,hi1,lo1).
#define TILE_R  64
#define NTILES  (SK / TILE_R)               // 2048
#define ZP      132                          // zs stride in float2
#define ZS_FLOATS (TILE_R * ZP * 2)         // 16896 floats
#define WF_FLOAT4S (16 * 16 * 32)           // 8192 float4 = 131072 B
#define SMEMB   (ZS_FLOATS * 4 + WF_FLOAT4S * 16)   // 67584 + 131072 = 198656
#define GRID_G  148
#define GTHR    256

template <int MODE>
__global__ __launch_bounds__(GTHR)
void gemm_kernel(const float* __restrict__ W, const float* __restrict__ bias,
                 const float* __restrict__ eps, int l, int zero_next,
                 const int* __restrict__ node_ids) {
    extern __shared__ float sm[];
    float2* zs = (float2*)sm;                  // [64][132] (hi,lo) pairs
    float4* wf = (float4*)(sm + ZS_FLOATS);    // [k0b 16][i 16][lane 32] frag-packed

    const int tid  = threadIdx.x;
    const int w    = tid >> 5;
    const int lane = tid & 31;
    const int gid  = lane >> 2;        // 0..7
    const int tig  = lane & 3;         // 0..3
    const int wr   = (w & 1) * 32;     // warp row offset (0/32), covers 32 rows
    const int wc   = (w >> 1) * 32;    // warp col offset (0/32/64/96)
    const int ib0  = (w >> 1) * 4;     // first n-block (8 cols each) of this warp

    // ---- stage W^T pre-split into fragment-packed layout (once per kernel)
#pragma unroll
    for (int i = 0; i < 16; i++) {
        int idx4 = tid + i * GTHR;
        int k  = idx4 >> 5;
        int n0 = (idx4 & 31) << 2;
        float4 w4 = ((const float4*)W)[idx4];
        float wv[4] = {w4.x, w4.y, w4.z, w4.w};
        int k0b = k >> 3, kk = k & 7, tg = kk & 3, sh = kk >> 2;
#pragma unroll
        for (int j = 0; j < 4; j++) {
            int n = n0 + j;
            uint32_t hb, lb;
            split_tf32(wv[j], hb, lb);
            float2* dstp = (float2*)&wf[(k0b * 16 + (n >> 3)) * 32 + ((n & 7) * 4 + tg)];
            dstp[sh] = make_float2(__uint_as_float(hb), __uint_as_float(lb));
        }
    }

    // ---- bias for this thread's 8 columns, in registers
    float bcol[8];
#pragma unroll
    for (int i = 0; i < 4; i++) {
        float2 b2 = *(const float2*)&bias[wc + 8 * i + 2 * tig];
        bcol[2 * i] = b2.x; bcol[2 * i + 1] = b2.y;
    }
    const float epsl = (MODE == 1) ? (1.0f + eps[l]) : 0.0f;

    // per-thread staging coordinates: 8 float4 slots (64 rows x 32 float4-cols)
    int srow[8], scol[8];
#pragma unroll
    for (int i = 0; i < 8; i++) {
        int idx4 = tid + i * GTHR;
        srow[i] = idx4 >> 5;
        scol[i] = (idx4 & 31) << 2;
    }
    __syncthreads();

    // ---- pipeline prologue: load first tile into registers
    float4 ph[8], pa[8];
    {
        const int row0 = blockIdx.x * TILE_R;
#pragma unroll
        for (int i = 0; i < 8; i++) {
            if (MODE == 1) {
                ph[i] = *(const float4*)&g_h[(row0 + srow[i]) * H + scol[i]];
                pa[i] = *(const float4*)&g_aggr[(row0 + srow[i]) * H + scol[i]];
            } else {
                ph[i] = *(const float4*)&g_mid[(row0 + srow[i]) * H + scol[i]];
            }
        }
    }

    const float4* wbase = wf + ib0 * 32 + lane;   // base for W fragment loads

    for (int t = blockIdx.x; t < NTILES; t += gridDim.x) {
        const int row0 = t * TILE_R;

        // ---- phase 1: split registers -> zs (packed STS.128), zero aggr[t]
#pragma unroll
        for (int i = 0; i < 8; i++) {
            float zv[4];
            if (MODE == 1) {
                zv[0] = epsl * ph[i].x + pa[i].x;
                zv[1] = epsl * ph[i].y + pa[i].y;
                zv[2] = epsl * ph[i].z + pa[i].z;
                zv[3] = epsl * ph[i].w + pa[i].w;
                if (zero_next)
                    *(float4*)&g_aggr[(row0 + srow[i]) * H + scol[i]] =
                        make_float4(0.f, 0.f, 0.f, 0.f);
            } else {
                zv[0] = ph[i].x; zv[1] = ph[i].y; zv[2] = ph[i].z; zv[3] = ph[i].w;
            }
            uint32_t hb[4], lb[4];
#pragma unroll
            for (int j = 0; j < 4; j++) split_tf32(zv[j], hb[j], lb[j]);
            float4* zrow4 = (float4*)&zs[srow[i] * ZP + scol[i]];
            zrow4[0] = make_float4(__uint_as_float(hb[0]), __uint_as_float(lb[0]),
                                   __uint_as_float(hb[1]), __uint_as_float(lb[1]));
            zrow4[1] = make_float4(__uint_as_float(hb[2]), __uint_as_float(lb[2]),
                                   __uint_as_float(hb[3]), __uint_as_float(lb[3]));
        }
        __syncthreads();

        // ---- phase 2a: prefetch next tile (latency covered by K loop)
        {
            int tn = t + gridDim.x;
            int tc = (tn < NTILES) ? tn : t;      // clamp; discarded on last iter
            const int rn0 = tc * TILE_R;
#pragma unroll
            for (int i = 0; i < 8; i++) {
                if (MODE == 1) {
                    ph[i] = *(const float4*)&g_h[(rn0 + srow[i]) * H + scol[i]];
                    pa[i] = *(const float4*)&g_aggr[(rn0 + srow[i]) * H + scol[i]];
                } else {
                    ph[i] = *(const float4*)&g_mid[(rn0 + srow[i]) * H + scol[i]];
                }
            }
        }

        // ---- phase 2b: accumulators + K loop (2 m-frags x 4 n-frags)
        float acc[2][4][4];
#pragma unroll
        for (int m = 0; m < 2; m++)
#pragma unroll
            for (int i = 0; i < 4; i++) {
                acc[m][i][0] = bcol[2 * i];     acc[m][i][1] = bcol[2 * i + 1];
                acc[m][i][2] = bcol[2 * i];     acc[m][i][3] = bcol[2 * i + 1];
            }

        const float2* za = &zs[(wr + gid) * ZP + tig];        // row wr+gid
#pragma unroll 4
        for (int k0b = 0; k0b < 16; k0b++) {
            const int k0 = k0b * 8;
            uint32_t ah[2][4], al[2][4];
#pragma unroll
            for (int m = 0; m < 2; m++) {
                const float2* zm = za + m * 16 * ZP;
                float2 p0 = zm[k0];
                float2 p1 = zm[8 * ZP + k0];
                float2 p2 = zm[k0 + 4];
                float2 p3 = zm[8 * ZP + k0 + 4];
                ah[m][0] = __float_as_uint(p0.x); al[m][0] = __float_as_uint(p0.y);
                ah[m][1] = __float_as_uint(p1.x); al[m][1] = __float_as_uint(p1.y);
                ah[m][2] = __float_as_uint(p2.x); al[m][2] = __float_as_uint(p2.y);
                ah[m][3] = __float_as_uint(p3.x); al[m][3] = __float_as_uint(p3.y);
            }
#pragma unroll
            for (int i = 0; i < 4; i++) {
                float4 wv = wbase[k0b * 512 + i * 32];   // LDS.128, conflict-free
                uint32_t bh0 = __float_as_uint(wv.x), bl0 = __float_as_uint(wv.y);
                uint32_t bh1 = __float_as_uint(wv.z), bl1 = __float_as_uint(wv.w);
#pragma unroll
                for (int m = 0; m < 2; m++) {
                    mma_tf32(acc[m][i], ah[m][0], ah[m][1], ah[m][2], ah[m][3], bh0, bh1);
                    mma_tf32(acc[m][i], al[m][0], al[m][1], al[m][2], al[m][3], bh0, bh1);
                    mma_tf32(acc[m][i], ah[m][0], ah[m][1], ah[m][2], ah[m][3], bl0, bl1);
                }
            }
        }

        // ---- phase 3: epilogue straight to global
        float* dstb = (MODE == 1) ? g_mid : g_h;
#pragma unroll
        for (int m = 0; m < 2; m++) {
            const int r0g = row0 + wr + m * 16 + gid;
            const int r1g = r0g + 8;
            float vf0 = 1.0f, vf1 = 1.0f;
            if (MODE == 2) {
                vf0 = (node_ids[r0g] >= 0) ? 1.0f : 0.0f;
                vf1 = (node_ids[r1g] >= 0) ? 1.0f : 0.0f;
            }
#pragma unroll
            for (int i = 0; i < 4; i++) {
                int n = wc + 8 * i + 2 * tig;
                float2 v0, v1;
                if (MODE == 1) {
                    v0 = make_float2(fmaxf(acc[m][i][0], 0.f), fmaxf(acc[m][i][1], 0.f));
                    v1 = make_float2(fmaxf(acc[m][i][2], 0.f), fmaxf(acc[m][i][3], 0.f));
                } else {
                    v0 = make_float2(acc[m][i][0] * vf0, acc[m][i][1] * vf0);
                    v1 = make_float2(acc[m][i][2] * vf1, acc[m][i][3] * vf1);
                }
                *(float2*)&dstb[r0g * H + n] = v0;
                *(float2*)&dstb[r1g * H + n] = v1;
            }
        }
        __syncthreads();   // all reads of zs done before next store phase
    }
}

// ================= pooling =================
__global__ void zero_out_kernel(float* __restrict__ out, int n) {
    int i = blockIdx.x * blockDim.x + threadIdx.x;
    if (i < n) out[i] = 0.0f;
}

__global__ void pool_kernel(const int* __restrict__ node_ids,
                            const float* __restrict__ log_probs,
                            const int* __restrict__ batch_graph,
                            const float* __restrict__ ht_alpha,
                            float* __restrict__ out) {
    __shared__ float wgt[M_SUB];
    __shared__ float cinv[M_SUB];
    __shared__ int   nid_s[M_SUB * K_SUB];
    int n = blockIdx.x;
    int tid = threadIdx.x;

    if (tid < M_SUB * K_SUB) nid_s[tid] = node_ids[n * (M_SUB * K_SUB) + tid];
    __syncthreads();

    if (tid < M_SUB) {
        int c = 0;
#pragma unroll
        for (int kk = 0; kk < K_SUB; kk++) c += (nid_s[tid * K_SUB + kk] >= 0);
        cinv[tid] = 1.0f / fmaxf((float)c, 1.0f);
    }
    if (tid == 0) {
        float alpha = ht_alpha[0];
        float v[M_SUB];
        float mx = -3.4e38f;
#pragma unroll
        for (int mm = 0; mm < M_SUB; mm++) {
            float lp = log_probs[n * M_SUB + mm];
            if (!isfinite(lp)) lp = 0.0f;
            v[mm] = -alpha * lp;
            mx = fmaxf(mx, v[mm]);
        }
        float sum = 0.0f;
#pragma unroll
        for (int mm = 0; mm < M_SUB; mm++) { v[mm] = expf(v[mm] - mx); sum += v[mm]; }
#pragma unroll
        for (int mm = 0; mm < M_SUB; mm++) wgt[mm] = v[mm] / sum;
    }
    __syncthreads();

    int d = tid;
    float val = 0.0f;
#pragma unroll
    for (int mm = 0; mm < M_SUB; mm++) {
        float s = 0.0f;
#pragma unroll
        for (int kk = 0; kk < K_SUB; kk++) {
            int fi = n * (M_SUB * K_SUB) + mm * K_SUB + kk;
            if (nid_s[mm * K_SUB + kk] >= 0) s += g_h[fi * H + d];
        }
        val += wgt[mm] * s * cinv[mm];
    }
    atomicAdd(&out[batch_graph[n] * H + d], val);
}

// ================= launch =================
extern "C" void kernel_launch(void* const* d_in, const int* in_sizes, int n_in,
                              void* d_out, int out_size) {
    const int*   x_tokens    = (const int*)d_in[0];
    const int*   edge_tokens = (const int*)d_in[1];
    const int*   intra_ei    = (const int*)d_in[2];
    const int*   node_ids    = (const int*)d_in[3];
    const float* log_probs   = (const float*)d_in[6];
    const int*   batch_graph = (const int*)d_in[7];
    const float* atom_emb    = (const float*)d_in[8];
    const float* bond_emb    = (const float*)d_in[9];
    const float* role_emb    = (const float*)d_in[10];
    const float* eps         = (const float*)d_in[11];
    const float* w1          = (const float*)d_in[12];
    const float* b1          = (const float*)d_in[13];
    const float* w2          = (const float*)d_in[14];
    const float* b2          = (const float*)d_in[15];
    const float* ht_alpha    = (const float*)d_in[16];
    float* out = (float*)d_out;

    const int* src = intra_ei;
    const int* dst = intra_ei + E_CNT;

    (void)cudaFuncSetAttribute(gemm_kernel<1>, cudaFuncAttributeMaxDynamicSharedMemorySize, SMEMB);
    (void)cudaFuncSetAttribute(gemm_kernel<2>, cudaFuncAttributeMaxDynamicSharedMemorySize, SMEMB);

    embed_kernel<<<(SK * 32) / 256, 256>>>(x_tokens, node_ids, atom_emb, role_emb);
    zero_aggr_kernel<<<(SK * H / 4) / 256, 256>>>();

    for (int l = 0; l < L_LAYERS; l++) {
        edge_kernel<<<(E_CNT * 32) / 256, 256>>>(src, dst, edge_tokens, bond_emb);
        gemm_kernel<1><<<GRID_G, GTHR, SMEMB>>>(
            w1 + l * H * H, b1 + l * H, eps, l, (l < L_LAYERS - 1) ? 1 : 0, node_ids);
        gemm_kernel<2><<<GRID_G, GTHR, SMEMB>>>(
            w2 + l * H * H, b2 + l * H, (const float*)0, 0, 0, node_ids);
    }

    zero_out_kernel<<<(NUM_G * H + 255) / 256, 256>>>(out, NUM_G * H);
    pool_kernel<<<N_TOT, H>>>(node_ids, log_probs, batch_graph, ht_alpha, out);
}

// round 13
// speedup vs baseline: 1.2355x; 1.2355x over previous
#include <cuda_runtime.h>
#include <math.h>
#include <stdint.h>

#define SK        131072
#define E_CNT     196608
#define H         128
#define N_TOT     4096
#define M_SUB     4
#define K_SUB     8
#define L_LAYERS  4
#define NUM_G     32

// ---------------- scratch (static device memory; no allocations) ----------------
__device__ float g_h[SK * H];     // node features (64 MB)
__device__ float g_aggr[SK * H];  // (1+eps_l)*h + message accumulation (64 MB)
__device__ float g_mid[SK * H];   // relu intermediate between the two GEMMs (64 MB)

// ---------------- 3xTF32 helpers ----------------
__device__ __forceinline__ void split_tf32(float z, uint32_t& hi, uint32_t& lo) {
    uint32_t zb = __float_as_uint(z);
    hi = zb & 0xFFFFE000u;
    lo = __float_as_uint(z - __uint_as_float(hi));
}

__device__ __forceinline__ void mma_tf32(float* c,
                                         uint32_t a0, uint32_t a1, uint32_t a2, uint32_t a3,
                                         uint32_t b0, uint32_t b1) {
    asm volatile(
        "mma.sync.aligned.m16n8k8.row.col.f32.tf32.tf32.f32 "
        "{%0,%1,%2,%3}, {%4,%5,%6,%7}, {%8,%9}, {%0,%1,%2,%3};"
        : "+f"(c[0]), "+f"(c[1]), "+f"(c[2]), "+f"(c[3])
        : "r"(a0), "r"(a1), "r"(a2), "r"(a3), "r"(b0), "r"(b1));
}

// ================= small kernels =================
// embed: h0 -> g_h ; (1+eps[0])*h0 -> g_aggr (edge messages accumulate on top)
__global__ void embed_kernel(const int* __restrict__ x_tokens,
                             const int* __restrict__ node_ids,
                             const float* __restrict__ atom_emb,
                             const float* __restrict__ role_emb,
                             const float* __restrict__ eps) {
    int t = blockIdx.x * blockDim.x + threadIdx.x;
    int node = t >> 5;
    int lane = t & 31;
    int tok = x_tokens[node];
    float vf = (node_ids[node] >= 0) ? 1.0f : 0.0f;
    int is_root = ((node & (K_SUB - 1)) == 0) ? 1 : 0;
    int c = lane * 4;
    float e0 = 1.0f + eps[0];
    float4 a = *(const float4*)(&atom_emb[tok * H + c]);
    float4 r = *(const float4*)(&role_emb[is_root * H + c]);
    float4 o;
    o.x = (a.x + r.x) * vf; o.y = (a.y + r.y) * vf;
    o.z = (a.z + r.z) * vf; o.w = (a.w + r.w) * vf;
    *(float4*)(&g_h[node * H + c]) = o;
    *(float4*)(&g_aggr[node * H + c]) =
        make_float4(e0 * o.x, e0 * o.y, e0 * o.z, e0 * o.w);
}

__global__ void edge_kernel(const int* __restrict__ src,
                            const int* __restrict__ dst,
                            const int* __restrict__ etok,
                            const float* __restrict__ bond_emb) {
    int t = blockIdx.x * blockDim.x + threadIdx.x;
    int e = t >> 5;
    if (e >= E_CNT) return;
    int lane = t & 31;
    int s = src[e], d = dst[e], bt = etok[e];
    int c = lane * 4;
    float4 hv = *(const float4*)(&g_h[s * H + c]);
    float4 bv = *(const float4*)(&bond_emb[bt * H + c]);
    float4 m;
    m.x = fmaxf(hv.x + bv.x, 0.f); m.y = fmaxf(hv.y + bv.y, 0.f);
    m.z = fmaxf(hv.z + bv.z, 0.f); m.w = fmaxf(hv.w + bv.w, 0.f);
    float* zp = &g_aggr[d * H + c];
    asm volatile("red.global.add.v4.f32 [%0], {%1, %2, %3, %4};"
                 :: "l"(zp), "f"(m.x), "f"(m.y), "f"(m.z), "f"(m.w) : "memory");
}

// ================= 3xTF32 mma.sync GEMM (pipelined, 128-row tile) ==============
// MODE 1: Z = g_aggr (already (1+eps)h+msgs) ; out = relu(Z@W1+b1) -> g_mid
// MODE 2: Z = g_mid ; h = (Z@W2+b2)*vf -> g_h ; if prep_next: (1+eps[ln])*h -> g_aggr
//
// Persistent (grid=148, 1 block/SM). 512 threads = 16 warps (4 row x 4 col groups).
// Block tile 128x128, warp tile 32x32 -> per-row W LDS traffic of the (2x4) config
// with doubled warp count. zs UNSPLIT floats (A split in-loop: 16 ALU/warp-k-step);
// W pre-split frag-packed float4 (hi0,lo0,hi1,lo1), conflict-free LDS.128.
#define TILE_R  128
#define NTILES  (SK / TILE_R)               // 1024
#define ZP      132                          // zs stride in floats
#define ZS_FLOATS (TILE_R * ZP)             // 16896 floats = 67584 B
#define WF_FLOAT4S (16 * 16 * 32)           // 8192 float4 = 131072 B
#define SMEMB   (ZS_FLOATS * 4 + WF_FLOAT4S * 16)   // 198656 B
#define GRID_G  148
#define GTHR    512

template <int MODE>
__global__ __launch_bounds__(GTHR, 1)
void gemm_kernel(const float* __restrict__ W, const float* __restrict__ bias,
                 const float* __restrict__ eps, int lnext, int prep_next,
                 const int* __restrict__ node_ids) {
    extern __shared__ float sm[];
    float*  zs = sm;                           // [128][132] floats (unsplit)
    float4* wf = (float4*)(sm + ZS_FLOATS);    // [k0b 16][nb 16][lane 32] frag-packed

    const int tid  = threadIdx.x;
    const int w    = tid >> 5;
    const int lane = tid & 31;
    const int gid  = lane >> 2;        // 0..7
    const int tig  = lane & 3;         // 0..3
    const int wr   = (w & 3) * 32;     // warp row offset (0/32/64/96)
    const int wc   = (w >> 2) * 32;    // warp col offset (0/32/64/96)
    const int ib0  = (w >> 2) * 4;     // first n-block (8 cols) of this warp

    // ---- stage W^T pre-split into fragment-packed layout (once per kernel)
#pragma unroll
    for (int i = 0; i < 8; i++) {
        int idx4 = tid + i * GTHR;
        int k  = idx4 >> 5;
        int n0 = (idx4 & 31) << 2;
        float4 w4 = ((const float4*)W)[idx4];
        float wv[4] = {w4.x, w4.y, w4.z, w4.w};
        int k0b = k >> 3, kk = k & 7, tg = kk & 3, sh = kk >> 2;
#pragma unroll
        for (int j = 0; j < 4; j++) {
            int n = n0 + j;
            uint32_t hb, lb;
            split_tf32(wv[j], hb, lb);
            float2* dstp = (float2*)&wf[(k0b * 16 + (n >> 3)) * 32 + ((n & 7) * 4 + tg)];
            dstp[sh] = make_float2(__uint_as_float(hb), __uint_as_float(lb));
        }
    }

    // ---- bias for this thread's 8 columns, in registers
    float bcol[8];
#pragma unroll
    for (int i = 0; i < 4; i++) {
        float2 b2 = *(const float2*)&bias[wc + 8 * i + 2 * tig];
        bcol[2 * i] = b2.x; bcol[2 * i + 1] = b2.y;
    }
    const float epsn = (MODE == 2 && prep_next) ? (1.0f + eps[lnext]) : 0.0f;

    // per-thread staging coordinates: 8 float4 slots (128 rows x 32 float4-cols)
    int srow[8], scol[8];
#pragma unroll
    for (int i = 0; i < 8; i++) {
        int idx4 = tid + i * GTHR;
        srow[i] = idx4 >> 5;
        scol[i] = (idx4 & 31) << 2;
    }
    __syncthreads();

    const float* srcb = (MODE == 1) ? g_aggr : g_mid;

    // ---- pipeline prologue: load first tile into registers
    float4 pz[8];
    {
        const int row0 = blockIdx.x * TILE_R;
#pragma unroll
        for (int i = 0; i < 8; i++)
            pz[i] = *(const float4*)&srcb[(row0 + srow[i]) * H + scol[i]];
    }

    const float4* wbase = wf + ib0 * 32 + lane;   // base for W fragment loads

    for (int t = blockIdx.x; t < NTILES; t += gridDim.x) {
        const int row0 = t * TILE_R;

        // ---- phase 1: registers -> zs (unsplit, STS.128)
#pragma unroll
        for (int i = 0; i < 8; i++)
            *(float4*)&zs[srow[i] * ZP + scol[i]] = pz[i];
        __syncthreads();

        // ---- phase 2a: prefetch next tile (latency covered by K loop)
        {
            int tn = t + gridDim.x;
            int tc = (tn < NTILES) ? tn : t;      // clamp; discarded on last iter
            const int rn0 = tc * TILE_R;
#pragma unroll
            for (int i = 0; i < 8; i++)
                pz[i] = *(const float4*)&srcb[(rn0 + srow[i]) * H + scol[i]];
        }

        // ---- phase 2b: accumulators + K loop (2 m-frags x 4 n-frags per warp)
        float acc[2][4][4];
#pragma unroll
        for (int m = 0; m < 2; m++)
#pragma unroll
            for (int i = 0; i < 4; i++) {
                acc[m][i][0] = bcol[2 * i];     acc[m][i][1] = bcol[2 * i + 1];
                acc[m][i][2] = bcol[2 * i];     acc[m][i][3] = bcol[2 * i + 1];
            }

        const float* za = &zs[(wr + gid) * ZP + tig];        // row wr+gid
#pragma unroll 4
        for (int k0b = 0; k0b < 16; k0b++) {
            const int k0 = k0b * 8;
            uint32_t ah[2][4], al[2][4];
#pragma unroll
            for (int m = 0; m < 2; m++) {
                const float* zm = za + m * 16 * ZP;
                split_tf32(zm[k0],               ah[m][0], al[m][0]);
                split_tf32(zm[8 * ZP + k0],      ah[m][1], al[m][1]);
                split_tf32(zm[k0 + 4],           ah[m][2], al[m][2]);
                split_tf32(zm[8 * ZP + k0 + 4],  ah[m][3], al[m][3]);
            }
#pragma unroll
            for (int i = 0; i < 4; i++) {
                float4 wv = wbase[k0b * 512 + i * 32];   // LDS.128, conflict-free
                uint32_t bh0 = __float_as_uint(wv.x), bl0 = __float_as_uint(wv.y);
                uint32_t bh1 = __float_as_uint(wv.z), bl1 = __float_as_uint(wv.w);
#pragma unroll
                for (int m = 0; m < 2; m++) {
                    mma_tf32(acc[m][i], ah[m][0], ah[m][1], ah[m][2], ah[m][3], bh0, bh1);
                    mma_tf32(acc[m][i], al[m][0], al[m][1], al[m][2], al[m][3], bh0, bh1);
                    mma_tf32(acc[m][i], ah[m][0], ah[m][1], ah[m][2], ah[m][3], bl0, bl1);
                }
            }
        }

        // ---- phase 3: epilogue straight to global
#pragma unroll
        for (int m = 0; m < 2; m++) {
            const int r0g = row0 + wr + m * 16 + gid;
            const int r1g = r0g + 8;
            float vf0 = 1.0f, vf1 = 1.0f;
            if (MODE == 2) {
                vf0 = (node_ids[r0g] >= 0) ? 1.0f : 0.0f;
                vf1 = (node_ids[r1g] >= 0) ? 1.0f : 0.0f;
            }
#pragma unroll
            for (int i = 0; i < 4; i++) {
                int n = wc + 8 * i + 2 * tig;
                if (MODE == 1) {
                    *(float2*)&g_mid[r0g * H + n] =
                        make_float2(fmaxf(acc[m][i][0], 0.f), fmaxf(acc[m][i][1], 0.f));
                    *(float2*)&g_mid[r1g * H + n] =
                        make_float2(fmaxf(acc[m][i][2], 0.f), fmaxf(acc[m][i][3], 0.f));
                } else {
                    float2 v0 = make_float2(acc[m][i][0] * vf0, acc[m][i][1] * vf0);
                    float2 v1 = make_float2(acc[m][i][2] * vf1, acc[m][i][3] * vf1);
                    *(float2*)&g_h[r0g * H + n] = v0;
                    *(float2*)&g_h[r1g * H + n] = v1;
                    if (prep_next) {
                        *(float2*)&g_aggr[r0g * H + n] =
                            make_float2(epsn * v0.x, epsn * v0.y);
                        *(float2*)&g_aggr[r1g * H + n] =
                            make_float2(epsn * v1.x, epsn * v1.y);
                    }
                }
            }
        }
        __syncthreads();   // all reads of zs done before next store phase
    }
}

// ================= pooling =================
__global__ void zero_out_kernel(float* __restrict__ out, int n) {
    int i = blockIdx.x * blockDim.x + threadIdx.x;
    if (i < n) out[i] = 0.0f;
}

__global__ void pool_kernel(const int* __restrict__ node_ids,
                            const float* __restrict__ log_probs,
                            const int* __restrict__ batch_graph,
                            const float* __restrict__ ht_alpha,
                            float* __restrict__ out) {
    __shared__ float wgt[M_SUB];
    __shared__ float cinv[M_SUB];
    __shared__ int   nid_s[M_SUB * K_SUB];
    int n = blockIdx.x;
    int tid = threadIdx.x;

    if (tid < M_SUB * K_SUB) nid_s[tid] = node_ids[n * (M_SUB * K_SUB) + tid];
    __syncthreads();

    if (tid < M_SUB) {
        int c = 0;
#pragma unroll
        for (int kk = 0; kk < K_SUB; kk++) c += (nid_s[tid * K_SUB + kk] >= 0);
        cinv[tid] = 1.0f / fmaxf((float)c, 1.0f);
    }
    if (tid == 0) {
        float alpha = ht_alpha[0];
        float v[M_SUB];
        float mx = -3.4e38f;
#pragma unroll
        for (int mm = 0; mm < M_SUB; mm++) {
            float lp = log_probs[n * M_SUB + mm];
            if (!isfinite(lp)) lp = 0.0f;
            v[mm] = -alpha * lp;
            mx = fmaxf(mx, v[mm]);
        }
        float sum = 0.0f;
#pragma unroll
        for (int mm = 0; mm < M_SUB; mm++) { v[mm] = expf(v[mm] - mx); sum += v[mm]; }
#pragma unroll
        for (int mm = 0; mm < M_SUB; mm++) wgt[mm] = v[mm] / sum;
    }
    __syncthreads();

    int d = tid;
    float val = 0.0f;
#pragma unroll
    for (int mm = 0; mm < M_SUB; mm++) {
        float s = 0.0f;
#pragma unroll
        for (int kk = 0; kk < K_SUB; kk++) {
            int fi = n * (M_SUB * K_SUB) + mm * K_SUB + kk;
            if (nid_s[mm * K_SUB + kk] >= 0) s += g_h[fi * H + d];
        }
        val += wgt[mm] * s * cinv[mm];
    }
    atomicAdd(&out[batch_graph[n] * H + d], val);
}

// ================= launch =================
extern "C" void kernel_launch(void* const* d_in, const int* in_sizes, int n_in,
                              void* d_out, int out_size) {
    const int*   x_tokens    = (const int*)d_in[0];
    const int*   edge_tokens = (const int*)d_in[1];
    const int*   intra_ei    = (const int*)d_in[2];
    const int*   node_ids    = (const int*)d_in[3];
    const float* log_probs   = (const float*)d_in[6];
    const int*   batch_graph = (const int*)d_in[7];
    const float* atom_emb    = (const float*)d_in[8];
    const float* bond_emb    = (const float*)d_in[9];
    const float* role_emb    = (const float*)d_in[10];
    const float* eps         = (const float*)d_in[11];
    const float* w1          = (const float*)d_in[12];
    const float* b1          = (const float*)d_in[13];
    const float* w2          = (const float*)d_in[14];
    const float* b2          = (const float*)d_in[15];
    const float* ht_alpha    = (const float*)d_in[16];
    float* out = (float*)d_out;

    const int* src = intra_ei;
    const int* dst = intra_ei + E_CNT;

    (void)cudaFuncSetAttribute(gemm_kernel<1>, cudaFuncAttributeMaxDynamicSharedMemorySize, SMEMB);
    (void)cudaFuncSetAttribute(gemm_kernel<2>, cudaFuncAttributeMaxDynamicSharedMemorySize, SMEMB);

    embed_kernel<<<(SK * 32) / 256, 256>>>(x_tokens, node_ids, atom_emb, role_emb, eps);

    for (int l = 0; l < L_LAYERS; l++) {
        edge_kernel<<<(E_CNT * 32) / 256, 256>>>(src, dst, edge_tokens, bond_emb);
        gemm_kernel<1><<<GRID_G, GTHR, SMEMB>>>(
            w1 + l * H * H, b1 + l * H, eps, 0, 0, node_ids);
        gemm_kernel<2><<<GRID_G, GTHR, SMEMB>>>(
            w2 + l * H * H, b2 + l * H, eps, l + 1,
            (l < L_LAYERS - 1) ? 1 : 0, node_ids);
    }

    zero_out_kernel<<<(NUM_G * H + 255) / 256, 256>>>(out, NUM_G * H);
    pool_kernel<<<N_TOT, H>>>(node_ids, log_probs, batch_graph, ht_alpha, out);
}